// round 11
// baseline (speedup 1.0000x reference)
#include <cuda_runtime.h>
#include <cstdint>

// SpatialTransformer: 2D bilinear warp per depth slice, align_corners=True,
// zero padding. src [B,C,D,H,W] f32, v [B,2,D,H,W] f32, out f32.
// H==W so normalization cancels: ix = x + vx, iy = y + vy.
//
// One-shot blocks (R6/R10 structure) with PER-CHANNEL TMA mbarriers:
// channel-major gather waits only on the channel it is about to read, so
// only ch0's ~13KB fill latency is exposed; ch1-3 stream in behind the
// ch0 gather. RB=8 output rows, staged rows r0-3..r0+9 (TR=13) -> 53KB tile.
// Out-of-band rows (~0.3% of pixels) fall back to global __ldg.

constexpr int B = 8, C = 4, D = 32, H = 256, W = 256;
constexpr int HW  = H * W;
constexpr int DHW = D * HW;
constexpr int RB  = 8;                 // output rows per block
constexpr int MLO = 3, MHI = 2;        // staged margin below/above
constexpr int TR  = RB + MLO + MHI;    // 13 staged rows max
constexpr int TPB = 256;               // 8 warps; 1 output row per warp
constexpr int HP  = 4;                 // pixels per half (2 halves = 8 px/thread)
constexpr int TILE_ELEMS = TR * W;     // 3328 floats per channel
constexpr int NBLK = B * D * (H / RB); // 8192
constexpr size_t SMEM_BYTES = (size_t)C * TILE_ELEMS * 4 + 64;

__device__ __forceinline__ uint32_t s2u(const void* p) {
    return (uint32_t)__cvta_generic_to_shared(p);
}

struct Coords {
    int   o00[HP], o01[HP], o10[HP], o11[HP];
    float k00[HP], k01[HP], k10[HP], k11[HP];
};

__device__ __forceinline__ void compute_coords(
    Coords& cc, const float* __restrict__ vx_row, const float* __restrict__ vy_row,
    int lane, int y, int p0, int r_lo, int r_hi)
{
#pragma unroll
    for (int p = 0; p < HP; p++) {
        const int x = lane + 32 * (p0 + p);
        const float vx = __ldg(vx_row + x);
        const float vy = __ldg(vy_row + x);
        const float ix = (float)x + vx;
        const float iy = (float)y + vy;
        const float x0f = floorf(ix), y0f = floorf(iy);
        const float fx = ix - x0f, fy = iy - y0f;
        const int x0 = (int)x0f, y0 = (int)y0f;
        const int x1 = x0 + 1,   y1 = y0 + 1;

        const float mx0 = (x0 >= 0 && x0 < W) ? 1.0f : 0.0f;
        const float mx1 = (x1 >= 0 && x1 < W) ? 1.0f : 0.0f;
        const float my0 = (y0 >= 0 && y0 < H) ? 1.0f : 0.0f;
        const float my1 = (y1 >= 0 && y1 < H) ? 1.0f : 0.0f;

        const int x0c = min(max(x0, 0), W - 1);
        const int x1c = min(max(x1, 0), W - 1);
        const int y0c = min(max(y0, 0), H - 1);
        const int y1c = min(max(y1, 0), H - 1);

        const float gx0 = 1.0f - fx, gy0 = 1.0f - fy;
        cc.k00[p] = gx0 * gy0 * (mx0 * my0);
        cc.k01[p] = fx  * gy0 * (mx1 * my0);
        cc.k10[p] = gx0 * fy  * (mx0 * my1);
        cc.k11[p] = fx  * fy  * (mx1 * my1);

        if (y0c >= r_lo && y1c < r_hi) {
            const int row0 = (y0c - r_lo) * W, row1 = (y1c - r_lo) * W;
            cc.o00[p] = row0 + x0c; cc.o01[p] = row0 + x1c;
            cc.o10[p] = row1 + x0c; cc.o11[p] = row1 + x1c;
        } else {
            // slow path: encode global plane offsets as ~g (negative)
            cc.o00[p] = ~(y0c * W + x0c); cc.o01[p] = ~(y0c * W + x1c);
            cc.o10[p] = ~(y1c * W + x0c); cc.o11[p] = ~(y1c * W + x1c);
        }
    }
}

// Gather one channel's contribution for one half of the pixels.
__device__ __forceinline__ void gather_store_ch(
    const Coords& cc, const float* __restrict__ tc,
    const float* __restrict__ sc, float* __restrict__ oc,
    int lane, int p0)
{
#pragma unroll
    for (int p = 0; p < HP; p++) {
        const int x = lane + 32 * (p0 + p);
        float acc;
        if (cc.o00[p] >= 0) {
            acc =      tc[cc.o00[p]] * cc.k00[p];
            acc = fmaf(tc[cc.o01[p]], cc.k01[p], acc);
            acc = fmaf(tc[cc.o10[p]], cc.k10[p], acc);
            acc = fmaf(tc[cc.o11[p]], cc.k11[p], acc);
        } else {
            acc =      __ldg(sc + ~cc.o00[p]) * cc.k00[p];
            acc = fmaf(__ldg(sc + ~cc.o01[p]), cc.k01[p], acc);
            acc = fmaf(__ldg(sc + ~cc.o10[p]), cc.k10[p], acc);
            acc = fmaf(__ldg(sc + ~cc.o11[p]), cc.k11[p], acc);
        }
        oc[x] = acc;
    }
}

__device__ __forceinline__ void wait_full(uint32_t mb)
{
    uint32_t done;
    do {
        asm volatile(
            "{.reg .pred p; mbarrier.try_wait.parity.acquire.cta.shared::cta.b64 "
            "p, [%1], %2; selp.b32 %0, 1, 0, p;}"
            : "=r"(done) : "r"(mb), "r"(0u) : "memory");
    } while (!done);
}

__global__ __launch_bounds__(TPB, 4)
void st_kernel(const float* __restrict__ src,
               const float* __restrict__ v,
               float* __restrict__ out)
{
    extern __shared__ float smem[];
    float* tile = smem;  // [C][TILE_ELEMS]
    const uint32_t mb_base = s2u(smem + C * TILE_ELEMS);  // 4 mbarriers

    const int blk = blockIdx.x;
    const int rt  = blk & (H / RB - 1);   // 32 row-tiles
    const int bd  = blk >> 5;
    const int d   = bd & (D - 1);
    const int b   = bd >> 5;
    const int r0  = rt * RB;
    const int r_lo = max(0, r0 - MLO);
    const int r_hi = min(H, r0 + RB + MHI);
    const int nrows = r_hi - r_lo;

    const float* splane = src + (size_t)(b * C) * DHW + (size_t)d * HW;

    if (threadIdx.x == 0) {
#pragma unroll
        for (int c = 0; c < C; c++) {
            asm volatile("mbarrier.init.shared.b64 [%0], 1;"
                         :: "r"(mb_base + 8 * c) : "memory");
        }
    }
    __syncthreads();
    if (threadIdx.x == 0) {
        const int bytes = nrows * W * 4;
#pragma unroll
        for (int c = 0; c < C; c++) {
            const uint32_t mb = mb_base + 8 * c;
            asm volatile("mbarrier.arrive.expect_tx.shared.b64 _, [%0], %1;"
                         :: "r"(mb), "r"(bytes) : "memory");
            const uint32_t dst = s2u(tile + c * TILE_ELEMS);
            const float* gsrc = splane + (size_t)c * DHW + r_lo * W;
            asm volatile(
                "cp.async.bulk.shared::cluster.global.mbarrier::complete_tx::bytes "
                "[%0], [%1], %2, [%3];"
                :: "r"(dst), "l"(gsrc), "r"(bytes), "r"(mb) : "memory");
        }
    }

    const int warp = threadIdx.x >> 5, lane = threadIdx.x & 31;
    const int y = r0 + warp;
    const float* vx_row = v + (size_t)(b * 2) * DHW + (size_t)d * HW + y * W;
    const float* vy_row = vx_row + DHW;
    float* obase = out + (size_t)(b * C) * DHW + (size_t)d * HW + y * W;

    // half 1 coords overlap the ch0 fill
    Coords cc;
    compute_coords(cc, vx_row, vy_row, lane, y, 0, r_lo, r_hi);

    // channel-major: wait only for the channel about to be gathered;
    // later channels stream in behind the earlier gathers.
#pragma unroll
    for (int c = 0; c < C; c++) {
        wait_full(mb_base + 8 * c);
        gather_store_ch(cc, tile + c * TILE_ELEMS, splane + (size_t)c * DHW,
                        obase + (size_t)c * DHW, lane, 0);
    }

    // half 2: all channels already resident, no waits
    compute_coords(cc, vx_row, vy_row, lane, y, HP, r_lo, r_hi);
#pragma unroll
    for (int c = 0; c < C; c++) {
        gather_store_ch(cc, tile + c * TILE_ELEMS, splane + (size_t)c * DHW,
                        obase + (size_t)c * DHW, lane, HP);
    }
}

extern "C" void kernel_launch(void* const* d_in, const int* in_sizes, int n_in,
                              void* d_out, int out_size)
{
    const float* src = (const float*)d_in[0];
    const float* v   = (const float*)d_in[1];
    float* out       = (float*)d_out;

    cudaFuncSetAttribute(st_kernel,
                         cudaFuncAttributeMaxDynamicSharedMemorySize,
                         (int)SMEM_BYTES);
    cudaFuncSetAttribute(st_kernel,
                         cudaFuncAttributePreferredSharedMemoryCarveout,
                         cudaSharedmemCarveoutMaxShared);
    st_kernel<<<NBLK, TPB, SMEM_BYTES>>>(src, v, out);
}

// round 12
// speedup vs baseline: 1.5291x; 1.5291x over previous
#include <cuda_runtime.h>
#include <cstdint>

// SpatialTransformer: 2D bilinear warp per depth slice, align_corners=True,
// zero padding. src [B,C,D,H,W] f32, v [B,2,D,H,W] f32, out f32.
// H==W so normalization cancels: ix = x + vx, iy = y + vy.
//
// R6 structure (best so far): one-shot 512-thread block, monolithic TMA band
// load -> coords overlap -> single mbarrier wait -> dense LDS gather.
// Change vs R6: margin trimmed +-4 -> +-3 (TR=22 staged rows per 16 output
// rows, staging overlap 1.5x -> 1.375x). P(|vy|>3) ~ 0.27% of pixels take
// the global-__ldg slow path. 88KB tile, 2 blocks/SM, 32 warps/SM.

constexpr int B = 8, C = 4, D = 32, H = 256, W = 256;
constexpr int HW  = H * W;
constexpr int DHW = D * HW;
constexpr int RB  = 16;                // output rows per block
constexpr int MGN = 3;                 // staged row margin (|vy|<=3 fast path)
constexpr int TR  = RB + 2 * MGN;      // 22 staged rows max
constexpr int TPB = 512;               // 16 warps; 1 output row per warp
constexpr int HP  = 4;                 // pixels per half (2 halves = 8 px/thread)
constexpr int TILE_ELEMS = TR * W;     // 5632 floats per channel
constexpr int NBLK = B * D * (H / RB); // 4096
constexpr size_t SMEM_BYTES = (size_t)C * TILE_ELEMS * 4 + 16;  // ~88 KB

__device__ __forceinline__ uint32_t s2u(const void* p) {
    return (uint32_t)__cvta_generic_to_shared(p);
}

struct Coords {
    int   o00[HP], o01[HP], o10[HP], o11[HP];
    float k00[HP], k01[HP], k10[HP], k11[HP];
};

__device__ __forceinline__ void compute_coords(
    Coords& cc, const float* __restrict__ vx_row, const float* __restrict__ vy_row,
    int lane, int y, int p0, int r_lo, int r_hi)
{
#pragma unroll
    for (int p = 0; p < HP; p++) {
        const int x = lane + 32 * (p0 + p);
        const float vx = __ldg(vx_row + x);
        const float vy = __ldg(vy_row + x);
        const float ix = (float)x + vx;
        const float iy = (float)y + vy;
        const float x0f = floorf(ix), y0f = floorf(iy);
        const float fx = ix - x0f, fy = iy - y0f;
        const int x0 = (int)x0f, y0 = (int)y0f;
        const int x1 = x0 + 1,   y1 = y0 + 1;

        const float mx0 = (x0 >= 0 && x0 < W) ? 1.0f : 0.0f;
        const float mx1 = (x1 >= 0 && x1 < W) ? 1.0f : 0.0f;
        const float my0 = (y0 >= 0 && y0 < H) ? 1.0f : 0.0f;
        const float my1 = (y1 >= 0 && y1 < H) ? 1.0f : 0.0f;

        const int x0c = min(max(x0, 0), W - 1);
        const int x1c = min(max(x1, 0), W - 1);
        const int y0c = min(max(y0, 0), H - 1);
        const int y1c = min(max(y1, 0), H - 1);

        const float gx0 = 1.0f - fx, gy0 = 1.0f - fy;
        cc.k00[p] = gx0 * gy0 * (mx0 * my0);
        cc.k01[p] = fx  * gy0 * (mx1 * my0);
        cc.k10[p] = gx0 * fy  * (mx0 * my1);
        cc.k11[p] = fx  * fy  * (mx1 * my1);

        if (y0c >= r_lo && y1c < r_hi) {
            const int row0 = (y0c - r_lo) * W, row1 = (y1c - r_lo) * W;
            cc.o00[p] = row0 + x0c; cc.o01[p] = row0 + x1c;
            cc.o10[p] = row1 + x0c; cc.o11[p] = row1 + x1c;
        } else {
            // slow path: encode global plane offsets as ~g (negative)
            cc.o00[p] = ~(y0c * W + x0c); cc.o01[p] = ~(y0c * W + x1c);
            cc.o10[p] = ~(y1c * W + x0c); cc.o11[p] = ~(y1c * W + x1c);
        }
    }
}

__device__ __forceinline__ void gather_store(
    const Coords& cc, const float* __restrict__ tile,
    const float* __restrict__ splane, float* __restrict__ obase,
    int lane, int p0)
{
#pragma unroll
    for (int p = 0; p < HP; p++) {
        const int x = lane + 32 * (p0 + p);
        if (cc.o00[p] >= 0) {
#pragma unroll
            for (int c = 0; c < C; c++) {
                const float* tc = tile + c * TILE_ELEMS;
                float acc =      tc[cc.o00[p]] * cc.k00[p];
                acc = fmaf(tc[cc.o01[p]], cc.k01[p], acc);
                acc = fmaf(tc[cc.o10[p]], cc.k10[p], acc);
                acc = fmaf(tc[cc.o11[p]], cc.k11[p], acc);
                obase[(size_t)c * DHW + x] = acc;
            }
        } else {
            const int g00 = ~cc.o00[p], g01 = ~cc.o01[p];
            const int g10 = ~cc.o10[p], g11 = ~cc.o11[p];
#pragma unroll
            for (int c = 0; c < C; c++) {
                const float* sc = splane + (size_t)c * DHW;
                float acc =      __ldg(sc + g00) * cc.k00[p];
                acc = fmaf(__ldg(sc + g01), cc.k01[p], acc);
                acc = fmaf(__ldg(sc + g10), cc.k10[p], acc);
                acc = fmaf(__ldg(sc + g11), cc.k11[p], acc);
                obase[(size_t)c * DHW + x] = acc;
            }
        }
    }
}

__global__ __launch_bounds__(TPB, 2)
void st_kernel(const float* __restrict__ src,
               const float* __restrict__ v,
               float* __restrict__ out)
{
    extern __shared__ float smem[];
    float* tile = smem;  // [C][TILE_ELEMS]
    unsigned long long* mbar = (unsigned long long*)(smem + C * TILE_ELEMS);

    const int blk = blockIdx.x;
    const int rt  = blk & (H / RB - 1);   // 16 row-tiles
    const int bd  = blk >> 4;
    const int d   = bd & (D - 1);
    const int b   = bd >> 5;
    const int r0  = rt * RB;
    const int r_lo = max(0, r0 - MGN);
    const int r_hi = min(H, r0 + RB + MGN);
    const int nrows = r_hi - r_lo;

    const float* splane = src + (size_t)(b * C) * DHW + (size_t)d * HW;

    const uint32_t mb = s2u(mbar);
    if (threadIdx.x == 0) {
        asm volatile("mbarrier.init.shared.b64 [%0], 1;" :: "r"(mb) : "memory");
    }
    __syncthreads();
    if (threadIdx.x == 0) {
        const int bytes = nrows * W * 4;
        asm volatile("mbarrier.arrive.expect_tx.shared.b64 _, [%0], %1;"
                     :: "r"(mb), "r"(bytes * C) : "memory");
#pragma unroll
        for (int c = 0; c < C; c++) {
            const uint32_t dst = s2u(tile + c * TILE_ELEMS);
            const float* gsrc = splane + (size_t)c * DHW + r_lo * W;
            asm volatile(
                "cp.async.bulk.shared::cluster.global.mbarrier::complete_tx::bytes "
                "[%0], [%1], %2, [%3];"
                :: "r"(dst), "l"(gsrc), "r"(bytes), "r"(mb) : "memory");
        }
    }

    const int warp = threadIdx.x >> 5, lane = threadIdx.x & 31;
    const int y = r0 + warp;
    const float* vx_row = v + (size_t)(b * 2) * DHW + (size_t)d * HW + y * W;
    const float* vy_row = vx_row + DHW;
    float* obase = out + (size_t)(b * C) * DHW + (size_t)d * HW + y * W;

    // half 1 coords overlap the TMA
    Coords cc;
    compute_coords(cc, vx_row, vy_row, lane, y, 0, r_lo, r_hi);

    // wait for TMA tiles
    {
        uint32_t done;
        do {
            asm volatile(
                "{.reg .pred p; mbarrier.try_wait.parity.acquire.cta.shared::cta.b64 "
                "p, [%1], %2; selp.b32 %0, 1, 0, p;}"
                : "=r"(done) : "r"(mb), "r"(0u) : "memory");
        } while (!done);
    }

    gather_store(cc, tile, splane, obase, lane, 0);
    compute_coords(cc, vx_row, vy_row, lane, y, HP, r_lo, r_hi);
    gather_store(cc, tile, splane, obase, lane, HP);
}

extern "C" void kernel_launch(void* const* d_in, const int* in_sizes, int n_in,
                              void* d_out, int out_size)
{
    const float* src = (const float*)d_in[0];
    const float* v   = (const float*)d_in[1];
    float* out       = (float*)d_out;

    cudaFuncSetAttribute(st_kernel,
                         cudaFuncAttributeMaxDynamicSharedMemorySize,
                         (int)SMEM_BYTES);
    st_kernel<<<NBLK, TPB, SMEM_BYTES>>>(src, v, out);
}

// round 13
// speedup vs baseline: 1.5978x; 1.0450x over previous
#include <cuda_runtime.h>
#include <cstdint>

// SpatialTransformer: 2D bilinear warp per depth slice, align_corners=True,
// zero padding. src [B,C,D,H,W] f32, v [B,2,D,H,W] f32, out f32.
// H==W so normalization cancels: ix = x + vx, iy = y + vy.
//
// Champion structure (R6/R12): one-shot 512-thread block, monolithic TMA band
// load (16 output rows, +-3 margin, 88KB SoA tile, 2 blocks/SM) -> coords
// overlap -> single mbarrier wait -> dense LDS gather (bank = x mod 32).
// R13 deltas:
//  1. ALL v loads (both halves) hoisted before the mbarrier wait -- the asm
//     memory clobber otherwise pins half-2's 8 LDGs after the wait, exposing
//     a ~600-cycle DRAM bubble between the gather halves.
//  2. Output stores use __stcs (evict-first) so the out stream doesn't evict
//     src margin lines from L2.

constexpr int B = 8, C = 4, D = 32, H = 256, W = 256;
constexpr int HW  = H * W;
constexpr int DHW = D * HW;
constexpr int RB  = 16;                // output rows per block
constexpr int MGN = 3;                 // staged row margin (|vy|<=3 fast path)
constexpr int TR  = RB + 2 * MGN;      // 22 staged rows max
constexpr int TPB = 512;               // 16 warps; 1 output row per warp
constexpr int HP  = 4;                 // pixels per half (2 halves = 8 px/thread)
constexpr int TILE_ELEMS = TR * W;     // 5632 floats per channel
constexpr int NBLK = B * D * (H / RB); // 4096
constexpr size_t SMEM_BYTES = (size_t)C * TILE_ELEMS * 4 + 16;  // ~88 KB

__device__ __forceinline__ uint32_t s2u(const void* p) {
    return (uint32_t)__cvta_generic_to_shared(p);
}

struct Coords {
    int   o00[HP], o01[HP], o10[HP], o11[HP];
    float k00[HP], k01[HP], k10[HP], k11[HP];
};

__device__ __forceinline__ void coords_from_v(
    Coords& cc, const float* vx, const float* vy,
    int lane, int y, int p0, int r_lo, int r_hi)
{
#pragma unroll
    for (int p = 0; p < HP; p++) {
        const int x = lane + 32 * (p0 + p);
        const float ix = (float)x + vx[p];
        const float iy = (float)y + vy[p];
        const float x0f = floorf(ix), y0f = floorf(iy);
        const float fx = ix - x0f, fy = iy - y0f;
        const int x0 = (int)x0f, y0 = (int)y0f;
        const int x1 = x0 + 1,   y1 = y0 + 1;

        const float mx0 = (x0 >= 0 && x0 < W) ? 1.0f : 0.0f;
        const float mx1 = (x1 >= 0 && x1 < W) ? 1.0f : 0.0f;
        const float my0 = (y0 >= 0 && y0 < H) ? 1.0f : 0.0f;
        const float my1 = (y1 >= 0 && y1 < H) ? 1.0f : 0.0f;

        const int x0c = min(max(x0, 0), W - 1);
        const int x1c = min(max(x1, 0), W - 1);
        const int y0c = min(max(y0, 0), H - 1);
        const int y1c = min(max(y1, 0), H - 1);

        const float gx0 = 1.0f - fx, gy0 = 1.0f - fy;
        cc.k00[p] = gx0 * gy0 * (mx0 * my0);
        cc.k01[p] = fx  * gy0 * (mx1 * my0);
        cc.k10[p] = gx0 * fy  * (mx0 * my1);
        cc.k11[p] = fx  * fy  * (mx1 * my1);

        if (y0c >= r_lo && y1c < r_hi) {
            const int row0 = (y0c - r_lo) * W, row1 = (y1c - r_lo) * W;
            cc.o00[p] = row0 + x0c; cc.o01[p] = row0 + x1c;
            cc.o10[p] = row1 + x0c; cc.o11[p] = row1 + x1c;
        } else {
            // slow path: encode global plane offsets as ~g (negative)
            cc.o00[p] = ~(y0c * W + x0c); cc.o01[p] = ~(y0c * W + x1c);
            cc.o10[p] = ~(y1c * W + x0c); cc.o11[p] = ~(y1c * W + x1c);
        }
    }
}

__device__ __forceinline__ void gather_store(
    const Coords& cc, const float* __restrict__ tile,
    const float* __restrict__ splane, float* __restrict__ obase,
    int lane, int p0)
{
#pragma unroll
    for (int p = 0; p < HP; p++) {
        const int x = lane + 32 * (p0 + p);
        if (cc.o00[p] >= 0) {
#pragma unroll
            for (int c = 0; c < C; c++) {
                const float* tc = tile + c * TILE_ELEMS;
                float acc =      tc[cc.o00[p]] * cc.k00[p];
                acc = fmaf(tc[cc.o01[p]], cc.k01[p], acc);
                acc = fmaf(tc[cc.o10[p]], cc.k10[p], acc);
                acc = fmaf(tc[cc.o11[p]], cc.k11[p], acc);
                __stcs(obase + (size_t)c * DHW + x, acc);
            }
        } else {
            const int g00 = ~cc.o00[p], g01 = ~cc.o01[p];
            const int g10 = ~cc.o10[p], g11 = ~cc.o11[p];
#pragma unroll
            for (int c = 0; c < C; c++) {
                const float* sc = splane + (size_t)c * DHW;
                float acc =      __ldg(sc + g00) * cc.k00[p];
                acc = fmaf(__ldg(sc + g01), cc.k01[p], acc);
                acc = fmaf(__ldg(sc + g10), cc.k10[p], acc);
                acc = fmaf(__ldg(sc + g11), cc.k11[p], acc);
                __stcs(obase + (size_t)c * DHW + x, acc);
            }
        }
    }
}

__global__ __launch_bounds__(TPB, 2)
void st_kernel(const float* __restrict__ src,
               const float* __restrict__ v,
               float* __restrict__ out)
{
    extern __shared__ float smem[];
    float* tile = smem;  // [C][TILE_ELEMS]
    unsigned long long* mbar = (unsigned long long*)(smem + C * TILE_ELEMS);

    const int blk = blockIdx.x;
    const int rt  = blk & (H / RB - 1);   // 16 row-tiles
    const int bd  = blk >> 4;
    const int d   = bd & (D - 1);
    const int b   = bd >> 5;
    const int r0  = rt * RB;
    const int r_lo = max(0, r0 - MGN);
    const int r_hi = min(H, r0 + RB + MGN);
    const int nrows = r_hi - r_lo;

    const float* splane = src + (size_t)(b * C) * DHW + (size_t)d * HW;

    const uint32_t mb = s2u(mbar);
    if (threadIdx.x == 0) {
        asm volatile("mbarrier.init.shared.b64 [%0], 1;" :: "r"(mb) : "memory");
    }
    __syncthreads();
    if (threadIdx.x == 0) {
        const int bytes = nrows * W * 4;
        asm volatile("mbarrier.arrive.expect_tx.shared.b64 _, [%0], %1;"
                     :: "r"(mb), "r"(bytes * C) : "memory");
#pragma unroll
        for (int c = 0; c < C; c++) {
            const uint32_t dst = s2u(tile + c * TILE_ELEMS);
            const float* gsrc = splane + (size_t)c * DHW + r_lo * W;
            asm volatile(
                "cp.async.bulk.shared::cluster.global.mbarrier::complete_tx::bytes "
                "[%0], [%1], %2, [%3];"
                :: "r"(dst), "l"(gsrc), "r"(bytes), "r"(mb) : "memory");
        }
    }

    const int warp = threadIdx.x >> 5, lane = threadIdx.x & 31;
    const int y = r0 + warp;
    const float* vx_row = v + (size_t)(b * 2) * DHW + (size_t)d * HW + y * W;
    const float* vy_row = vx_row + DHW;
    float* obase = out + (size_t)(b * C) * DHW + (size_t)d * HW + y * W;

    // ---- all v loads + half-1 coords BEFORE the wait (overlap the TMA) ----
    float v1x[HP], v1y[HP], v2x[HP], v2y[HP];
#pragma unroll
    for (int p = 0; p < HP; p++) {
        const int x1i = lane + 32 * p;
        const int x2i = lane + 32 * (HP + p);
        v1x[p] = __ldg(vx_row + x1i);  v1y[p] = __ldg(vy_row + x1i);
        v2x[p] = __ldg(vx_row + x2i);  v2y[p] = __ldg(vy_row + x2i);
    }

    Coords cc;
    coords_from_v(cc, v1x, v1y, lane, y, 0, r_lo, r_hi);

    // wait for TMA tiles
    {
        uint32_t done;
        do {
            asm volatile(
                "{.reg .pred p; mbarrier.try_wait.parity.acquire.cta.shared::cta.b64 "
                "p, [%1], %2; selp.b32 %0, 1, 0, p;}"
                : "=r"(done) : "r"(mb), "r"(0u) : "memory");
        } while (!done);
    }

    gather_store(cc, tile, splane, obase, lane, 0);
    coords_from_v(cc, v2x, v2y, lane, y, HP, r_lo, r_hi);   // no memory ops
    gather_store(cc, tile, splane, obase, lane, HP);
}

extern "C" void kernel_launch(void* const* d_in, const int* in_sizes, int n_in,
                              void* d_out, int out_size)
{
    const float* src = (const float*)d_in[0];
    const float* v   = (const float*)d_in[1];
    float* out       = (float*)d_out;

    cudaFuncSetAttribute(st_kernel,
                         cudaFuncAttributeMaxDynamicSharedMemorySize,
                         (int)SMEM_BYTES);
    st_kernel<<<NBLK, TPB, SMEM_BYTES>>>(src, v, out);
}